// round 4
// baseline (speedup 1.0000x reference)
#include <cuda_runtime.h>
#include <cuda_bf16.h>
#include <cstdint>

// ---------------------------------------------------------------------------
// Problem constants (shapes are fixed by the dataset)
// ---------------------------------------------------------------------------
#define N_NODES   50000
#define N_EDGES   800000
#define DIM       128      // IN_DIM == OUT_DIM == 128
#define NUM_HEADS 8
#define HEAD_DIM  16

// ---------------------------------------------------------------------------
// Scratch (device globals; no allocation allowed in kernel_launch)
// ---------------------------------------------------------------------------
__device__ float g_Q[(size_t)N_NODES * DIM];
__device__ float g_K[(size_t)N_NODES * DIM];
__device__ float g_V[(size_t)N_NODES * DIM];
__device__ float g_E[(size_t)N_EDGES * DIM];
__device__ float g_Z[(size_t)N_NODES * NUM_HEADS];

// ---------------------------------------------------------------------------
// 128-wide SGEMM with bias: C[M,128] = A[M,128] @ W[128,128] + b
// 128x128 tile, BK=16, 256 threads, 8x8 microtile, DOUBLE-BUFFERED smem.
// ---------------------------------------------------------------------------
#define BM 128
#define BN 128
#define BK 16
#define TM 8
#define TN 8
#define NKITER (DIM / BK)   // 8

__device__ __forceinline__
void gemm128_body(const float* __restrict__ A, const float* __restrict__ W,
                  const float* __restrict__ bias, float* __restrict__ C,
                  int M, int block_row)
{
    __shared__ float As[2][BK][BM + 1];   // [buf][k][m], +1 pad
    __shared__ float Bs[2][BK][BN];       // [buf][k][n]

    const int tid = threadIdx.x;               // 0..255
    const int tx = tid & 15;                   // 0..15  (output col group)
    const int ty = tid >> 4;                   // 0..15  (output row group)

    // Per-thread load coordinates (fixed across iterations):
    // A tile: 2 float4 loads -> rows ar0/ar1, col group ac4 (0,4,8,12)
    const int ar0 = tid >> 2;                  // 0..63
    const int ar1 = ar0 + 64;                  // 64..127
    const int ac4 = (tid & 3) * 4;
    // B tile: 2 float4 loads -> rows br0/br1, col bc4
    const int br0 = tid >> 5;                  // 0..7
    const int br1 = br0 + 8;                   // 8..15
    const int bc4 = (tid & 31) * 4;            // 0..124

    float acc[TM][TN];
#pragma unroll
    for (int i = 0; i < TM; i++)
#pragma unroll
        for (int j = 0; j < TN; j++) acc[i][j] = 0.f;

    const int gr0 = block_row + ar0;
    const int gr1 = block_row + ar1;

    // ---- prologue: load tile 0 directly into buffer 0 ----
    {
        float4 a0 = make_float4(0.f, 0.f, 0.f, 0.f);
        float4 a1 = make_float4(0.f, 0.f, 0.f, 0.f);
        if (gr0 < M) a0 = *reinterpret_cast<const float4*>(A + (size_t)gr0 * DIM + ac4);
        if (gr1 < M) a1 = *reinterpret_cast<const float4*>(A + (size_t)gr1 * DIM + ac4);
        float4 b0 = *reinterpret_cast<const float4*>(W + (size_t)br0 * DIM + bc4);
        float4 b1 = *reinterpret_cast<const float4*>(W + (size_t)br1 * DIM + bc4);

        As[0][ac4 + 0][ar0] = a0.x; As[0][ac4 + 1][ar0] = a0.y;
        As[0][ac4 + 2][ar0] = a0.z; As[0][ac4 + 3][ar0] = a0.w;
        As[0][ac4 + 0][ar1] = a1.x; As[0][ac4 + 1][ar1] = a1.y;
        As[0][ac4 + 2][ar1] = a1.z; As[0][ac4 + 3][ar1] = a1.w;
        *reinterpret_cast<float4*>(&Bs[0][br0][bc4]) = b0;
        *reinterpret_cast<float4*>(&Bs[0][br1][bc4]) = b1;
    }
    __syncthreads();

#pragma unroll
    for (int t = 0; t < NKITER; t++) {
        const int cur = t & 1;
        const int nxt = cur ^ 1;

        // ---- prefetch tile t+1 into registers (LDGs issued before compute) ----
        float4 pa0, pa1, pb0, pb1;
        if (t < NKITER - 1) {
            const int k0 = (t + 1) * BK;
            pa0 = make_float4(0.f, 0.f, 0.f, 0.f);
            pa1 = make_float4(0.f, 0.f, 0.f, 0.f);
            if (gr0 < M) pa0 = *reinterpret_cast<const float4*>(A + (size_t)gr0 * DIM + k0 + ac4);
            if (gr1 < M) pa1 = *reinterpret_cast<const float4*>(A + (size_t)gr1 * DIM + k0 + ac4);
            pb0 = *reinterpret_cast<const float4*>(W + (size_t)(k0 + br0) * DIM + bc4);
            pb1 = *reinterpret_cast<const float4*>(W + (size_t)(k0 + br1) * DIM + bc4);
        }

        // ---- compute on current buffer ----
#pragma unroll
        for (int k = 0; k < BK; k++) {
            float ra[TM], rb[TN];
#pragma unroll
            for (int i = 0; i < TM; i++) ra[i] = As[cur][k][ty * TM + i];
#pragma unroll
            for (int j = 0; j < TN; j++) rb[j] = Bs[cur][k][tx * TN + j];
#pragma unroll
            for (int i = 0; i < TM; i++)
#pragma unroll
                for (int j = 0; j < TN; j++)
                    acc[i][j] += ra[i] * rb[j];
        }

        // ---- store prefetched tile into the other buffer, single barrier ----
        if (t < NKITER - 1) {
            As[nxt][ac4 + 0][ar0] = pa0.x; As[nxt][ac4 + 1][ar0] = pa0.y;
            As[nxt][ac4 + 2][ar0] = pa0.z; As[nxt][ac4 + 3][ar0] = pa0.w;
            As[nxt][ac4 + 0][ar1] = pa1.x; As[nxt][ac4 + 1][ar1] = pa1.y;
            As[nxt][ac4 + 2][ar1] = pa1.z; As[nxt][ac4 + 3][ar1] = pa1.w;
            *reinterpret_cast<float4*>(&Bs[nxt][br0][bc4]) = pb0;
            *reinterpret_cast<float4*>(&Bs[nxt][br1][bc4]) = pb1;
            __syncthreads();
        }
    }

    // ---- epilogue: add bias, store ----
#pragma unroll
    for (int i = 0; i < TM; i++) {
        int gr = block_row + ty * TM + i;
        if (gr < M) {
#pragma unroll
            for (int j = 0; j < TN; j += 4) {
                int col = tx * TN + j;
                float4 o;
                o.x = acc[i][j + 0] + __ldg(bias + col + 0);
                o.y = acc[i][j + 1] + __ldg(bias + col + 1);
                o.z = acc[i][j + 2] + __ldg(bias + col + 2);
                o.w = acc[i][j + 3] + __ldg(bias + col + 3);
                *reinterpret_cast<float4*>(C + (size_t)gr * DIM + col) = o;
            }
        }
    }
}

// Fused QKV: grid.y in {0,1,2} selects (Wq->g_Q), (Wk->g_K), (Wv->g_V)
__global__ __launch_bounds__(256)
void gemm_qkv(const float* __restrict__ x,
              const float* __restrict__ Wq, const float* __restrict__ bq,
              const float* __restrict__ Wk, const float* __restrict__ bk,
              const float* __restrict__ Wv, const float* __restrict__ bv,
              int M)
{
    const float* W; const float* b; float* C;
    if (blockIdx.y == 0)      { W = Wq; b = bq; C = g_Q; }
    else if (blockIdx.y == 1) { W = Wk; b = bk; C = g_K; }
    else                      { W = Wv; b = bv; C = g_V; }
    gemm128_body(x, W, b, C, M, blockIdx.x * BM);
}

// Edge projection into g_E
__global__ __launch_bounds__(256)
void gemm_e(const float* __restrict__ A, const float* __restrict__ W,
            const float* __restrict__ bias, int M)
{
    gemm128_body(A, W, bias, g_E, M, blockIdx.x * BM);
}

// ---------------------------------------------------------------------------
// Zero the accumulators (d_out used as wV accumulator, g_Z for denominators)
// ---------------------------------------------------------------------------
__global__ void zero_kernel(float* __restrict__ out)
{
    size_t i = (size_t)blockIdx.x * blockDim.x + threadIdx.x;
    if (i < (size_t)N_NODES * DIM) out[i] = 0.f;
    if (i < (size_t)N_NODES * NUM_HEADS) g_Z[i] = 0.f;
}

// ---------------------------------------------------------------------------
// Edge attention: one warp per edge, grid-stride over edges.
// Lane l handles feature elements [4l, 4l+4). Head = l>>2; lanes 4h..4h+3
// form head h; per-head reduction via 2x shfl_xor.
// Scatter via red.global.add.v4.f32 (vectorized no-return reduction).
// ---------------------------------------------------------------------------
__global__ __launch_bounds__(256)
void edge_kernel(const int* __restrict__ ei, float* __restrict__ out, int nE)
{
    const int lane   = threadIdx.x & 31;
    const int warpId = (int)((blockIdx.x * blockDim.x + threadIdx.x) >> 5);
    const int nWarps = (int)((gridDim.x * blockDim.x) >> 5);
    const int fo     = lane * 4;                 // feature offset for this lane

    for (int e = warpId; e < nE; e += nWarps) {
        const int src = __ldg(ei + e);
        const int dst = __ldg(ei + nE + e);

        const float4 e4 = *reinterpret_cast<const float4*>(g_E + (size_t)e   * DIM + fo);
        const float4 k4 = *reinterpret_cast<const float4*>(g_K + (size_t)src * DIM + fo);
        const float4 q4 = *reinterpret_cast<const float4*>(g_Q + (size_t)dst * DIM + fo);

        float p = e4.x * (k4.x * q4.x)
                + e4.y * (k4.y * q4.y)
                + e4.z * (k4.z * q4.z)
                + e4.w * (k4.w * q4.w);
        // reduce over the 4 lanes of this head (16 features / 4 per lane)
        p += __shfl_xor_sync(0xffffffffu, p, 1);
        p += __shfl_xor_sync(0xffffffffu, p, 2);

        // score = exp(clip(sum * 1/sqrt(16), -5, 5))
        float s = __expf(fminf(fmaxf(p * 0.25f, -5.f), 5.f));

        const float4 v4 = *reinterpret_cast<const float4*>(g_V + (size_t)src * DIM + fo);
        float mx = v4.x * s, my = v4.y * s, mz = v4.z * s, mw = v4.w * s;

        float* addr = out + (size_t)dst * DIM + fo;
        asm volatile("red.global.add.v4.f32 [%0], {%1, %2, %3, %4};"
                     :: "l"(addr), "f"(mx), "f"(my), "f"(mz), "f"(mw)
                     : "memory");

        if ((lane & 3) == 0)
            atomicAdd(&g_Z[(size_t)dst * NUM_HEADS + (lane >> 2)], s);
    }
}

// ---------------------------------------------------------------------------
// Normalize: out[n, :] /= (Z[n, head] + 1e-6)
// One thread per float4 (4 consecutive features share a head since 4 | 16).
// ---------------------------------------------------------------------------
__global__ void norm_kernel(float* __restrict__ out)
{
    int i = blockIdx.x * blockDim.x + threadIdx.x;       // float4 index
    const int total = N_NODES * (DIM / 4);               // 50000 * 32
    if (i >= total) return;
    int n = i >> 5;            // node
    int q = i & 31;            // float4-within-row; head = q >> 2
    float z = g_Z[(size_t)n * NUM_HEADS + (q >> 2)];
    float invz = 1.f / (z + 1e-6f);
    float4* p = reinterpret_cast<float4*>(out) + i;
    float4 v = *p;
    v.x *= invz; v.y *= invz; v.z *= invz; v.w *= invz;
    *p = v;
}

// ---------------------------------------------------------------------------
// kernel_launch
// Inputs (metadata order):
//  0: x          [N, 128] f32
//  1: edge_attr  [E, 128] f32
//  2: edge_index [2, E]   i32
//  3: Wq [128,128]  4: bq [128]
//  5: Wk [128,128]  6: bk [128]
//  7: We [128,128]  8: be [128]
//  9: Wv [128,128] 10: bv [128]
// Output: [N, 128] f32
// ---------------------------------------------------------------------------
extern "C" void kernel_launch(void* const* d_in, const int* in_sizes, int n_in,
                              void* d_out, int out_size)
{
    const float* x         = (const float*)d_in[0];
    const float* edge_attr = (const float*)d_in[1];
    const int*   edge_idx  = (const int*)  d_in[2];
    const float* Wq = (const float*)d_in[3];
    const float* bq = (const float*)d_in[4];
    const float* Wk = (const float*)d_in[5];
    const float* bk = (const float*)d_in[6];
    const float* We = (const float*)d_in[7];
    const float* be = (const float*)d_in[8];
    const float* Wv = (const float*)d_in[9];
    const float* bv = (const float*)d_in[10];
    float* out = (float*)d_out;

    const int nNodes = in_sizes[0] / DIM;     // 50000
    const int nE     = in_sizes[1] / DIM;     // 800000

    // zero accumulators (covers both out and g_Z since N*8 < N*128)
    {
        size_t total = (size_t)nNodes * DIM;
        int threads = 256;
        int blocks = (int)((total + threads - 1) / threads);
        zero_kernel<<<blocks, threads>>>(out);
    }

    // node projections Q, K, V (fused into one launch; grid.y = which proj)
    {
        dim3 grid((nNodes + BM - 1) / BM, 3);
        gemm_qkv<<<grid, 256>>>(x, Wq, bq, Wk, bk, Wv, bv, nNodes);
    }

    // edge projection E
    {
        int blocks = (nE + BM - 1) / BM;
        gemm_e<<<blocks, 256>>>(edge_attr, We, be, nE);
    }

    // edge attention + scatter (persistent-ish grid, grid-stride over edges)
    {
        int blocks = 148 * 8;                        // 8 CTAs/SM x 148 SMs
        edge_kernel<<<blocks, 256>>>(edge_idx, out, nE);
    }

    // normalize
    {
        int total = nNodes * (DIM / 4);
        int threads = 256;
        int blocks = (total + threads - 1) / threads;
        norm_kernel<<<blocks, threads>>>(out);
    }
}